// round 13
// baseline (speedup 1.0000x reference)
#include <cuda_runtime.h>
#include <cuda_bf16.h>
#include <cstdint>

// inputs:  [B=32, 56, 56, C=256] fp32 ; routing: [32, 4] fp32
// out[b,h,w,j] = inputs[b,h,w, argmax(routing[b])*64 + j]  -> [32,56,56,64]
//
// R13: R12 (LDG reads + SMEM + bulk-store writes, 8.7us) with the per-CTA
// __syncthreads + single 16KB store replaced by PER-WARP 2KB bulk stores:
// each warp's output slice is contiguous, so warp does LDG x4 -> STS x4 ->
// __syncwarp -> lane0 cp.async.bulk of its own 2KB. No block barrier; no
// straggler-warp gating; store stream starts as soon as each warp's loads land.

namespace {
constexpr int B       = 32;
constexpr int HW      = 56 * 56;      // 3136 pixels per batch
constexpr int ROUTES  = 4;
constexpr int V       = 16;           // float4 per output pixel (64 floats)
constexpr int CV      = 64;           // float4 per input pixel (256 floats)
constexpr int THREADS = 256;
constexpr int PER_TH  = 4;            // float4 per thread
constexpr int WARP_F4 = 32 * PER_TH;                      // 128 f4 = 2KB/warp
constexpr int PER_BLK = THREADS * PER_TH;                 // 1024 f4 = 16KB
constexpr long long TOTAL_V4 = (long long)B * HW * V;     // 1,605,632
constexpr int BLOCKS  = (int)(TOTAL_V4 / PER_BLK);        // 1568 (exact)
constexpr int BLOCKS_PER_BATCH = BLOCKS / B;              // 49   (exact)
constexpr int WARP_BYTES = WARP_F4 * 16;                  // 2048
}

__global__ __launch_bounds__(THREADS)
void routing_gather_kernel(const float4* __restrict__ in4,
                           const float*  __restrict__ routing,
                           float4* __restrict__ out4)
{
    __shared__ alignas(128) float4 tile[PER_BLK];   // 16 KB, = output layout

    const int b = blockIdx.x / BLOCKS_PER_BATCH;    // const-divisor -> mulhi

    // argmax over 4 logits; uniform address across block -> L1 broadcast.
    const float* r = routing + b * ROUTES;
    float best = r[0];
    int route = 0;
#pragma unroll
    for (int k = 1; k < ROUTES; ++k) {
        float v = r[k];
        if (v > best) { best = v; route = k; }      // strict > = first-max tie
    }
    const int rbase = route * V;

    const int warp = threadIdx.x >> 5;
    const int lane = threadIdx.x & 31;
    const int local = warp * WARP_F4 + lane;        // warp slice is contiguous
    const int base  = blockIdx.x * PER_BLK + local;

    // 4 independent coalesced LDG.128 (front-batched).
    float4 v[PER_TH];
#pragma unroll
    for (int k = 0; k < PER_TH; ++k) {
        int idx = base + k * 32;          // global output float4 index
        int t   = idx >> 4;               // pixel index (b*HW + pix)
        int j   = idx & (V - 1);          // float4 within pixel
        v[k] = __ldg(&in4[(long long)t * CV + rbase + j]);
    }
    // STS into this warp's contiguous 2KB slice (conflict-free STS.128).
#pragma unroll
    for (int k = 0; k < PER_TH; ++k) {
        tile[local + k * 32] = v[k];
    }
    __syncwarp();

    // Per-warp bulk store: 2KB SMEM -> GMEM on the async copy engine.
    if (lane == 0) {
        uint32_t st = (uint32_t)__cvta_generic_to_shared(&tile[warp * WARP_F4]);
        float4* dst = out4 + (long long)blockIdx.x * PER_BLK + warp * WARP_F4;
        asm volatile("fence.proxy.async.shared::cta;" ::: "memory");
        asm volatile("cp.async.bulk.global.shared::cta.bulk_group [%0], [%1], %2;"
                     :: "l"(dst), "r"(st), "r"(WARP_BYTES) : "memory");
        asm volatile("cp.async.bulk.commit_group;" ::: "memory");
        // SMEM must stay live until the engine has read it.
        asm volatile("cp.async.bulk.wait_group 0;" ::: "memory");
    }
}

extern "C" void kernel_launch(void* const* d_in, const int* in_sizes, int n_in,
                              void* d_out, int out_size)
{
    const float4* in4     = (const float4*)d_in[0];
    const float*  routing = (const float*)d_in[1];
    float4*       out4    = (float4*)d_out;

    routing_gather_kernel<<<BLOCKS, THREADS>>>(in4, routing, out4);
}